// round 1
// baseline (speedup 1.0000x reference)
#include <cuda_runtime.h>
#include <cstdint>
#include <cstddef>

// ---------------- problem constants ----------------
#define NUM_HEADS 8
#define DHEAD 32
#define BLOCK_SZ 8
#define HALO 3
#define WIN 14          // BLOCK + 2*HALO
#define WINP 196        // WIN*WIN
#define NHB 12          // 96/8
#define NB 144          // 12*12
#define HW 96
#define SPATIAL 9216    // 96*96
#define BATCH 8
#define CIN 256
#define OQKV 768        // 256 q + 512 kv
#define SCALE 0.17677669529663687f

// scratch: qkv[b][o][s], o<256 -> q (head*32+d), o>=256 -> kv (256 + head*64 + c)
__device__ float g_qkv[(size_t)BATCH * OQKV * SPATIAL];

// ---------------- kernel 1: fused QKV projection GEMM ----------------
// C[b][o][s] = sum_c W[o][c] * x[b][c][s]
// tile 64x64, BK=16, 256 threads, 4x4 micro-tile
#define BM 64
#define BN 64
#define BK 16

__global__ void __launch_bounds__(256) qkv_gemm(
    const float* __restrict__ x,
    const float* __restrict__ qw,
    const float* __restrict__ kvw)
{
    __shared__ float As[BK][BM + 4];  // [k][m], padded
    __shared__ float Bs[BK][BN];

    const int b  = blockIdx.z;
    const int m0 = blockIdx.y * BM;
    const int n0 = blockIdx.x * BN;
    const int tid = threadIdx.x;

    const float* xb = x + (size_t)b * CIN * SPATIAL;

    const int tr = tid / 16;          // 0..15 (output row group)
    const int tc = tid % 16;          // 0..15 (output col group)

    // A load mapping: thread loads W[m0 + tid/4][k0 + (tid%4)*4 .. +3]
    const int a_row  = tid >> 2;      // 0..63
    const int a_col4 = (tid & 3) * 4; // 0,4,8,12
    // B load mapping: thread loads x[k0 + tid/16][n0 + (tid%16)*4 .. +3]
    const int b_row  = tid >> 4;      // 0..15
    const int b_col4 = (tid & 15) * 4;

    const int o_a = m0 + a_row;
    const float* wrow = (o_a < 256) ? (qw + (size_t)o_a * CIN)
                                    : (kvw + (size_t)(o_a - 256) * CIN);

    float acc[4][4];
#pragma unroll
    for (int i = 0; i < 4; i++)
#pragma unroll
        for (int j = 0; j < 4; j++) acc[i][j] = 0.f;

    for (int k0 = 0; k0 < CIN; k0 += BK) {
        float4 av = *(const float4*)(wrow + k0 + a_col4);
        As[a_col4 + 0][a_row] = av.x;
        As[a_col4 + 1][a_row] = av.y;
        As[a_col4 + 2][a_row] = av.z;
        As[a_col4 + 3][a_row] = av.w;

        float4 bv = *(const float4*)(xb + (size_t)(k0 + b_row) * SPATIAL + n0 + b_col4);
        *(float4*)&Bs[b_row][b_col4] = bv;

        __syncthreads();
#pragma unroll
        for (int k = 0; k < BK; k++) {
            float a[4], bb[4];
            *(float4*)a  = *(const float4*)&As[k][tr * 4];
            *(float4*)bb = *(const float4*)&Bs[k][tc * 4];
#pragma unroll
            for (int i = 0; i < 4; i++)
#pragma unroll
                for (int j = 0; j < 4; j++)
                    acc[i][j] += a[i] * bb[j];
        }
        __syncthreads();
    }

    float* outb = g_qkv + (size_t)b * OQKV * SPATIAL;
#pragma unroll
    for (int i = 0; i < 4; i++) {
        const int o = m0 + tr * 4 + i;
        float4 v = make_float4(acc[i][0], acc[i][1], acc[i][2], acc[i][3]);
        *(float4*)(outb + (size_t)o * SPATIAL + n0 + tc * 4) = v;
    }
}

// ---------------- kernel 2: halo attention ----------------
// grid (144 blocks, 64 batch-heads), 128 threads.
// thread: q = tid>>1 (0..63), half = tid&1 (splits the 196 k-positions into
// two 98-position halves: y rows [0,7) / [7,14)). Flash-style online softmax,
// halves combined via lane shuffles (adjacent lanes).
#define KV_STRIDE 68            // 64 channels + pad (conflict-free transpose stores)
#define SMEM_KV   (WINP * KV_STRIDE)        // 13328 floats
#define SMEM_REL  (27 * 33)                 // 891 floats each
#define SMEM_RH   (128 * 9)                 // per-thread rh[7] (stride 9)
#define SMEM_FLOATS (SMEM_KV + 2 * SMEM_REL + SMEM_RH)
#define SMEM_BYTES  (SMEM_FLOATS * 4)

__global__ void __launch_bounds__(128) halo_attn(
    const float* __restrict__ hrel,
    const float* __restrict__ wrel,
    float* __restrict__ out)
{
    extern __shared__ float smem[];
    float* sKV = smem;                       // [196][68] : [pos][c], c<32 K, c>=32 V
    float* sH  = smem + SMEM_KV;             // [27][33]
    float* sW  = sH + SMEM_REL;              // [27][33]
    float* sRH = sW + SMEM_REL;              // [128][ stride 9 ]

    const int tid = threadIdx.x;
    const int nbidx = blockIdx.x;            // 0..143
    const int bh = blockIdx.y;               // 0..63
    const int b = bh >> 3, head = bh & 7;
    const int by = nbidx / NHB, bx = nbidx % NHB;

    // ---- stage rel tables ----
    for (int idx = tid; idx < 27 * 32; idx += 128) {
        const int r = idx >> 5, d = idx & 31;
        sH[r * 33 + d] = hrel[idx];
        sW[r * 33 + d] = wrel[idx];
    }

    // ---- stage KV window (transpose: global c-major -> shared pos-major) ----
    const float* kvbase = g_qkv + ((size_t)b * OQKV + 256 + head * 64) * SPATIAL;
    for (int idx = tid; idx < 64 * WINP; idx += 128) {
        const int c = idx / WINP, p = idx % WINP;
        const int y = p / WIN, xx = p % WIN;
        const int gh = by * BLOCK_SZ + y - HALO;
        const int gw = bx * BLOCK_SZ + xx - HALO;
        float v = 0.f;
        if ((unsigned)gh < (unsigned)HW && (unsigned)gw < (unsigned)HW)
            v = kvbase[(size_t)c * SPATIAL + gh * HW + gw];
        sKV[p * KV_STRIDE + c] = v;
    }

    // ---- load Q row into registers ----
    const int q    = tid >> 1;
    const int half = tid & 1;
    const int qi = q >> 3, qj = q & 7;
    const int sp = (by * BLOCK_SZ + qi) * HW + bx * BLOCK_SZ + qj;
    const float* qbase = g_qkv + ((size_t)b * OQKV + head * DHEAD) * SPATIAL + sp;

    float qr[32];
#pragma unroll
    for (int d = 0; d < 32; d++) qr[d] = qbase[(size_t)d * SPATIAL];

    __syncthreads();

    // ---- relative position terms ----
    // rw[x] = q . wrel[13 + x - qj] ; rh[y] = q . hrel[13 + y - qi]
    float rw[14];
#pragma unroll
    for (int xx = 0; xx < 14; xx++) {
        const float* wr = &sW[(13 + xx - qj) * 33];
        float s = 0.f;
#pragma unroll
        for (int d = 0; d < 32; d++) s += qr[d] * wr[d];
        rw[xx] = s;
    }
    const int y0 = half * 7;
    float* myrh = &sRH[tid * 9];
#pragma unroll
    for (int yy = 0; yy < 7; yy++) {
        const float* hr = &sH[(13 + y0 + yy - qi) * 33];
        float s = 0.f;
#pragma unroll
        for (int d = 0; d < 32; d++) s += qr[d] * hr[d];
        myrh[yy] = s;
    }
    // fold the QK scale into q
#pragma unroll
    for (int d = 0; d < 32; d++) qr[d] *= SCALE;

    // ---- flash loop over this half's 7 window rows ----
    float m = -1e30f, l = 0.f;
    float acc[32];
#pragma unroll
    for (int d = 0; d < 32; d++) acc[d] = 0.f;

    for (int yy = 0; yy < 7; yy++) {
        const float* kvp = sKV + (y0 + yy) * WIN * KV_STRIDE;
        const float rhv = myrh[yy];
        float lg[14];
        float rowm = -1e30f;
#pragma unroll
        for (int xx = 0; xx < 14; xx++) {
            const float4* kp4 = (const float4*)(kvp + xx * KV_STRIDE);
            float s0 = 0.f, s1 = 0.f, s2 = 0.f, s3 = 0.f;
#pragma unroll
            for (int dd = 0; dd < 8; dd++) {
                const float4 k4 = kp4[dd];
                s0 += qr[dd * 4 + 0] * k4.x;
                s1 += qr[dd * 4 + 1] * k4.y;
                s2 += qr[dd * 4 + 2] * k4.z;
                s3 += qr[dd * 4 + 3] * k4.w;
            }
            float s = (s0 + s1) + (s2 + s3) + rhv + rw[xx];
            lg[xx] = s;
            rowm = fmaxf(rowm, s);
        }
        const float mnew = fmaxf(m, rowm);
        const float corr = __expf(m - mnew);
        l *= corr;
#pragma unroll
        for (int d = 0; d < 32; d++) acc[d] *= corr;
#pragma unroll
        for (int xx = 0; xx < 14; xx++) {
            const float p_ = __expf(lg[xx] - mnew);
            l += p_;
            const float4* vp4 = (const float4*)(kvp + xx * KV_STRIDE + 32);
#pragma unroll
            for (int dd = 0; dd < 8; dd++) {
                const float4 v4 = vp4[dd];
                acc[dd * 4 + 0] += p_ * v4.x;
                acc[dd * 4 + 1] += p_ * v4.y;
                acc[dd * 4 + 2] += p_ * v4.z;
                acc[dd * 4 + 3] += p_ * v4.w;
            }
        }
        m = mnew;
    }

    // ---- combine the two halves (adjacent lanes) via shuffle ----
    const unsigned FULL = 0xFFFFFFFFu;
    const float m2 = __shfl_xor_sync(FULL, m, 1);
    const float M  = fmaxf(m, m2);
    const float w  = __expf(m - M);
    const float lw = l * w;
    const float L  = lw + __shfl_xor_sync(FULL, lw, 1);
    const float inv = 1.0f / L;

    float* ob = out + ((size_t)b * 256 + head * DHEAD) * SPATIAL + sp;
#pragma unroll
    for (int d = 0; d < 32; d++) {
        float a = acc[d] * w;
        a += __shfl_xor_sync(FULL, a, 1);
        if (half == 0) ob[(size_t)d * SPATIAL] = a * inv;
    }
}

// ---------------- launch ----------------
extern "C" void kernel_launch(void* const* d_in, const int* in_sizes, int n_in,
                              void* d_out, int out_size)
{
    const float* x    = (const float*)d_in[0];
    const float* qw   = (const float*)d_in[1];
    const float* kvw  = (const float*)d_in[2];
    const float* hrel = (const float*)d_in[3];
    const float* wrel = (const float*)d_in[4];
    float* out = (float*)d_out;

    cudaFuncSetAttribute(halo_attn, cudaFuncAttributeMaxDynamicSharedMemorySize,
                         SMEM_BYTES);

    qkv_gemm<<<dim3(SPATIAL / BN, OQKV / BM, BATCH), 256>>>(x, qw, kvw);
    halo_attn<<<dim3(NB, BATCH * NUM_HEADS), 128, SMEM_BYTES>>>(hrel, wrel, out);
}